// round 15
// baseline (speedup 1.0000x reference)
#include <cuda_runtime.h>
#include <cuda_bf16.h>
#include <cstdint>
#include <math.h>

#define BATCH 2
#define SEQ   2048
#define DMODEL 2048
#define NH    16
#define NKV   4
#define HD    128
#define ROPE  64
#define MTOK  (BATCH*SEQ)
#define EPSV  1.1920929e-07f

typedef __nv_bfloat16 bf16;

// ---------------- scratch ----------------
__device__ bf16 g_x3 [(size_t)MTOK*3*DMODEL];
__device__ bf16 g_qw3[(size_t)DMODEL*3*DMODEL];
__device__ bf16 g_kw3[(size_t)NKV*HD*3*DMODEL];
__device__ bf16 g_vw3[(size_t)NKV*HD*3*DMODEL];
__device__ bf16 g_ow3[(size_t)DMODEL*3*DMODEL];
__device__ bf16 g_Qp3[(size_t)BATCH*NH*SEQ*3*HD];
__device__ bf16 g_Kp3[(size_t)BATCH*NKV*SEQ*3*HD];
__device__ bf16 g_Vt3[(size_t)BATCH*NKV*HD*3*SEQ];
__device__ float g_S [(size_t)BATCH*NH*SEQ*SEQ];
__device__ bf16 g_Y3 [(size_t)MTOK*3*DMODEL];
__device__ unsigned g_RM[(size_t)BATCH*NH*SEQ];   // encoded row maxima

__device__ __forceinline__ void split2(float v, bf16& h, bf16& l) {
    h = __float2bfloat16_rn(v);
    l = __float2bfloat16_rn(v - __bfloat162float(h));
}
__device__ __forceinline__ uint32_t pk(bf16 a, bf16 b) {
    return (uint32_t)__bfloat16_as_ushort(a) | ((uint32_t)__bfloat16_as_ushort(b) << 16);
}
__device__ __forceinline__ unsigned enc_f(float f) {
    int i = __float_as_int(f);
    return (i >= 0) ? ((unsigned)i | 0x80000000u) : ~(unsigned)i;
}
__device__ __forceinline__ float dec_f(unsigned k) {
    int i = (k & 0x80000000u) ? (int)(k ^ 0x80000000u) : (int)(~k);
    return __int_as_float(i);
}
// triple writers for an even-d pair (3 u32, 4B-aligned)
__device__ __forceinline__ void w3A(bf16* p, float v0, float v1) {
    bf16 h0, l0, h1, l1; split2(v0, h0, l0); split2(v1, h1, l1);
    uint32_t* u = reinterpret_cast<uint32_t*>(p);
    u[0] = pk(h0, l0); u[1] = pk(h0, h1); u[2] = pk(l1, h1);
}
__device__ __forceinline__ void w3B(bf16* p, float v0, float v1) {
    bf16 h0, l0, h1, l1; split2(v0, h0, l0); split2(v1, h1, l1);
    uint32_t* u = reinterpret_cast<uint32_t*>(p);
    u[0] = pk(h0, h0); u[1] = pk(l0, h1); u[2] = pk(h1, l1);
}

// ---------------- PTX helpers (baseline PTX only) ----------------
__device__ __forceinline__ uint32_t smem_u32(const void* p) {
    uint32_t a;
    asm("{ .reg .u64 t; cvta.to.shared.u64 t, %1; cvt.u32.u64 %0, t; }" : "=r"(a) : "l"(p));
    return a;
}
__device__ __forceinline__ void ldsm4(uint32_t* r, uint32_t addr) {
    asm volatile("ldmatrix.sync.aligned.m8n8.x4.shared.b16 {%0,%1,%2,%3}, [%4];"
                 : "=r"(r[0]), "=r"(r[1]), "=r"(r[2]), "=r"(r[3]) : "r"(addr));
}
__device__ __forceinline__ void mma16816(float* c, const uint32_t* a, const uint32_t* b) {
    asm volatile(
        "mma.sync.aligned.m16n8k16.row.col.f32.bf16.bf16.f32 "
        "{%0,%1,%2,%3}, {%4,%5,%6,%7}, {%8,%9}, {%0,%1,%2,%3};"
        : "+f"(c[0]), "+f"(c[1]), "+f"(c[2]), "+f"(c[3])
        : "r"(a[0]), "r"(a[1]), "r"(a[2]), "r"(a[3]), "r"(b[0]), "r"(b[1]));
}
#define CP_ASYNC16(dst, src) \
    asm volatile("cp.async.cg.shared.global [%0], [%1], 16;" :: "r"(dst), "l"(src) : "memory")
#define CP_COMMIT() asm volatile("cp.async.commit_group;" ::: "memory")
#define CP_WAIT(n)  asm volatile("cp.async.wait_group %0;" :: "n"(n) : "memory")

// ---------------- settled GEMM config: chunk 32, 3 bufs, PADK 40 ----------------
#define PADK 40
#define TILEB (128*PADK*2)            // 10240 B
#define MM_SMEM (3*TILEB*2)           // 61440 B
#define QKV_SMEM (128*132*4)          // 67584 B staging (>= MM_SMEM)

struct MMState {
    uint32_t sAaddr, sBaddr;
    int aRow, aK, bRow, bK;
};

__device__ __forceinline__ void mm_mainloop(
    const bf16* gA, const bf16* gB, uint32_t dA, uint32_t dB,
    const MMState& st, int nc, float acc[4][4][4])
{
    #pragma unroll
    for (int j = 0; j < 2; j++) {
        if (j < nc) {
            const bf16* pA = gA + j * 32;
            const bf16* pB = gB + j * 32;
            CP_ASYNC16(dA + j * TILEB, pA);      CP_ASYNC16(dA + j * TILEB + 16, pA + 8);
            CP_ASYNC16(dB + j * TILEB, pB);      CP_ASYNC16(dB + j * TILEB + 16, pB + 8);
        }
        CP_COMMIT();
    }

    int buf = 0, nbuf = 2;
    for (int i = 0; i < nc; i++) {
        if (i < nc - 1) { CP_WAIT(1); } else { CP_WAIT(0); }
        __syncthreads();

        if (i + 2 < nc) {
            const bf16* pA = gA + (i + 2) * 32;
            const bf16* pB = gB + (i + 2) * 32;
            CP_ASYNC16(dA + nbuf * TILEB, pA);      CP_ASYNC16(dA + nbuf * TILEB + 16, pA + 8);
            CP_ASYNC16(dB + nbuf * TILEB, pB);      CP_ASYNC16(dB + nbuf * TILEB + 16, pB + 8);
        }
        CP_COMMIT();

        const uint32_t ab = st.sAaddr + buf * TILEB;
        const uint32_t bb = st.sBaddr + buf * TILEB;
        #pragma unroll
        for (int ks = 0; ks < 2; ks++) {
            uint32_t af[4][4], bfr[2][4];
            #pragma unroll
            for (int fm = 0; fm < 4; fm++)
                ldsm4(af[fm], ab + ((st.aRow + fm * 16) * PADK + ks * 16 + st.aK) * 2);
            #pragma unroll
            for (int bg = 0; bg < 2; bg++)
                ldsm4(bfr[bg], bb + ((st.bRow + bg * 16) * PADK + ks * 16 + st.bK) * 2);
            #pragma unroll
            for (int fm = 0; fm < 4; fm++)
                #pragma unroll
                for (int fn = 0; fn < 4; fn++)
                    mma16816(acc[fm][fn], af[fm], &bfr[fn >> 1][(fn & 1) * 2]);
        }

        buf = (buf == 2) ? 0 : buf + 1;
        nbuf = (nbuf == 2) ? 0 : nbuf + 1;
    }
}

__device__ __forceinline__ void mm_setup(MMState& st, char* smem, int t)
{
    st.sAaddr = smem_u32(smem);
    st.sBaddr = st.sAaddr + 3 * TILEB;
    const int w = t >> 5, lane = t & 31;
    const int wr = w >> 2, wc = w & 3;
    st.aRow = wr * 64 + (lane & 7) + ((lane >> 3) & 1) * 8;
    st.aK   = (lane >> 4) * 8;
    st.bRow = wc * 32 + (lane & 7) + ((lane >> 4) & 1) * 8;
    st.bK   = ((lane >> 3) & 1) * 8;
}

// ---------------- fused QKV projection + RMSNorm + RoPE + gain + split ----------------
__global__ void __launch_bounds__(256, 2) qkv_kernel(
    const bf16* __restrict__ X,
    const bf16* __restrict__ QW, const bf16* __restrict__ KW, const bf16* __restrict__ VW,
    bf16* __restrict__ Qp3, bf16* __restrict__ Kp3, bf16* __restrict__ Vt3,
    const float* __restrict__ gain)
{
    extern __shared__ __align__(16) char smem[];
    const int t = threadIdx.x;

    const int xt = blockIdx.x;            // 0..23: 0-15 Q heads, 16-19 K, 20-23 V
    const bf16* B;
    if (xt < 16)      B = QW;
    else if (xt < 20) B = KW;
    else              B = VW;
    const int n0 = (xt < 16) ? xt * 128 : ((xt < 20) ? (xt - 16) * 128 : (xt - 20) * 128);

    const int m0 = blockIdx.y * 128;
    const int K3 = 3 * DMODEL;
    const int nc = K3 >> 5;

    MMState st; mm_setup(st, smem, t);

    const int lr = t >> 1;
    const int lc = (t & 1) * 2;
    const bf16* gA = X + (long long)(m0 + lr) * K3 + lc * 8;
    const bf16* gB = B + (long long)(n0 + lr) * K3 + lc * 8;
    const uint32_t dA = st.sAaddr + (lr * PADK + lc * 8) * 2;
    const uint32_t dB = st.sBaddr + (lr * PADK + lc * 8) * 2;

    float acc[4][4][4];
    #pragma unroll
    for (int i = 0; i < 4; i++)
        #pragma unroll
        for (int j = 0; j < 4; j++)
            #pragma unroll
            for (int q = 0; q < 4; q++) acc[i][j][q] = 0.0f;

    mm_mainloop(gA, gB, dA, dB, st, nc, acc);

    // ---- stage fp32 tile to smem (pipeline bufs are dead) ----
    __syncthreads();
    float* sm = reinterpret_cast<float*>(smem);
    {
        const int w = t >> 5, lane = t & 31;
        const int wr = w >> 2, wc = w & 3;
        const int g = lane >> 2, tg = lane & 3;
        #pragma unroll
        for (int fm = 0; fm < 4; fm++)
            #pragma unroll
            for (int fn = 0; fn < 4; fn++)
                #pragma unroll
                for (int half = 0; half < 2; half++) {
                    const int row = wr * 64 + fm * 16 + g + half * 8;
                    const int col = wc * 32 + fn * 8 + tg * 2;
                    float2 f;
                    f.x = acc[fm][fn][half * 2];
                    f.y = acc[fm][fn][half * 2 + 1];
                    *reinterpret_cast<float2*>(&sm[row * 132 + col]) = f;
                }
    }
    __syncthreads();

    // ---- per-row postproc: thread t -> (row t>>1, 64-col half t&1) ----
    const int r = t >> 1, ch = t & 1, c0 = ch * 64;
    const int mg = m0 + r;
    const int b = mg / SEQ, s = mg % SEQ;
    const float* row = &sm[r * 132];

    if (xt < 20) {
        float ss = 0.0f;
        #pragma unroll
        for (int j = 0; j < 64; j += 4) {
            float4 v = *reinterpret_cast<const float4*>(row + c0 + j);
            ss += v.x * v.x + v.y * v.y + v.z * v.z + v.w * v.w;
        }
        ss += __shfl_xor_sync(0xFFFFFFFFu, ss, 1);
        const float rinv = rsqrtf(ss * (1.0f / 128.0f) + EPSV);

        const bool isQ = (xt < 16);
        const int h = isQ ? xt : xt - 16;
        const float gn = isQ ? gain[h] : 1.0f;
        bf16* base = isQ
            ? Qp3 + ((size_t)(b * NH  + h) * SEQ + s) * (3 * HD)
            : Kp3 + ((size_t)(b * NKV + h) * SEQ + s) * (3 * HD);

        if (ch == 0) {
            #pragma unroll 4
            for (int j = 0; j < 32; j += 2) {
                float o0[2], o1[2];
                #pragma unroll
                for (int q = 0; q < 2; q++) {
                    const int jj = j + q;
                    float x1 = row[jj] * rinv;
                    float x2 = row[jj + 32] * rinv;
                    float inv_freq = powf(10000.0f, -(float)jj / 32.0f);
                    float ang = (float)s * inv_freq;
                    float c = cosf(ang), sn = sinf(ang);
                    o0[q] = (x1 * c + x2 * sn) * gn;
                    o1[q] = (-x1 * sn + x2 * c) * gn;
                }
                if (isQ) { w3A(base + 3 * j, o0[0], o0[1]); w3A(base + 3 * (j + 32), o1[0], o1[1]); }
                else     { w3B(base + 3 * j, o0[0], o0[1]); w3B(base + 3 * (j + 32), o1[0], o1[1]); }
            }
        } else {
            #pragma unroll 8
            for (int j = 0; j < 64; j += 2) {
                float v0 = row[64 + j]     * rinv * gn;
                float v1 = row[64 + j + 1] * rinv * gn;
                if (isQ) w3A(base + 3 * (64 + j), v0, v1);
                else     w3B(base + 3 * (64 + j), v0, v1);
            }
        }
    } else {
        const int h = xt - 20;
        #pragma unroll 8
        for (int j = 0; j < 64; j++) {
            const int d = c0 + j;
            float v = row[d];
            bf16 hh, ll; split2(v, hh, ll);
            bf16* o = Vt3 + ((size_t)(b * NKV + h) * HD + d) * (3 * SEQ) + 3 * s;
            o[0] = hh; o[1] = hh; o[2] = ll;
        }
    }
}

// ---------------- general GEMM (scores / out-proj) ----------------
template<bool CAUSAL, bool BF16_OUT>
__global__ void __launch_bounds__(256, 2) mm_kernel(
    const bf16* __restrict__ A, const bf16* __restrict__ B,
    float* __restrict__ C, bf16* __restrict__ C3, unsigned* __restrict__ RM,
    int K3, int lda, int ldb, int ldc,
    long long sA, long long sB, long long sC, long long sC2,
    int bDiv, int cDiv, float alpha)
{
    extern __shared__ __align__(16) char smem[];
    const int t = threadIdx.x;

    const int z = blockIdx.z;
    A += (long long)z * sA;
    B += (long long)(z / bDiv) * sB;
    const long long cOff = (long long)(z / cDiv) * sC + (long long)(z % cDiv) * sC2;

    const int m0 = blockIdx.y * 128;
    const int n0 = blockIdx.x * 128;
    if (CAUSAL && n0 > m0 + 127) return;

    MMState st; mm_setup(st, smem, t);

    const int lr = t >> 1;
    const int lc = (t & 1) * 2;
    const int nc = K3 >> 5;

    const bf16* gA = A + (long long)(m0 + lr) * lda + lc * 8;
    const bf16* gB = B + (long long)(n0 + lr) * ldb + lc * 8;
    const uint32_t dA = st.sAaddr + (lr * PADK + lc * 8) * 2;
    const uint32_t dB = st.sBaddr + (lr * PADK + lc * 8) * 2;

    float acc[4][4][4];
    #pragma unroll
    for (int i = 0; i < 4; i++)
        #pragma unroll
        for (int j = 0; j < 4; j++)
            #pragma unroll
            for (int q = 0; q < 4; q++) acc[i][j][q] = 0.0f;

    mm_mainloop(gA, gB, dA, dB, st, nc, acc);

    const int w = t >> 5, lane = t & 31;
    const int wr = w >> 2, wc = w & 3;
    const int mBase = wr * 64, nBase = wc * 32;
    const int g = lane >> 2, tg = lane & 3;
    #pragma unroll
    for (int fm = 0; fm < 4; fm++) {
        float rmax[2];
        rmax[0] = -3.4e38f; rmax[1] = -3.4e38f;
        #pragma unroll
        for (int fn = 0; fn < 4; fn++) {
            const int col = n0 + nBase + fn * 8 + tg * 2;
            #pragma unroll
            for (int half = 0; half < 2; half++) {
                const int row = m0 + mBase + fm * 16 + g + half * 8;
                float v0 = acc[fm][fn][half * 2]     * alpha;
                float v1 = acc[fm][fn][half * 2 + 1] * alpha;
                if (BF16_OUT) {
                    bf16 h0, l0, h1, l1;
                    split2(v0, h0, l0); split2(v1, h1, l1);
                    uint32_t* dst = reinterpret_cast<uint32_t*>(
                        C3 + cOff + (long long)row * ldc + 3 * col);
                    dst[0] = pk(h0, l0);
                    dst[1] = pk(h0, h1);
                    dst[2] = pk(l1, h1);
                } else {
                    if (CAUSAL) {
                        if (col     > row) v0 = -1e30f;
                        if (col + 1 > row) v1 = -1e30f;
                        rmax[half] = fmaxf(rmax[half], fmaxf(v0, v1));
                    }
                    float2 f; f.x = v0; f.y = v1;
                    *reinterpret_cast<float2*>(C + cOff + (long long)row * ldc + col) = f;
                }
            }
        }
        if (CAUSAL) {
            #pragma unroll
            for (int half = 0; half < 2; half++) {
                float m = rmax[half];
                m = fmaxf(m, __shfl_xor_sync(0xFFFFFFFFu, m, 1));
                m = fmaxf(m, __shfl_xor_sync(0xFFFFFFFFu, m, 2));
                if (tg == 0) {
                    const int row = m0 + mBase + fm * 16 + g + half * 8;
                    atomicMax(RM + (long long)z * SEQ + row, enc_f(m));
                }
            }
        }
    }
}

// ---------------- rowmax init ----------------
__global__ void rm_init(unsigned* __restrict__ RM)
{
    RM[blockIdx.x * 256 + threadIdx.x] = 0u;
}

// ---------------- fused softmax + PV kernel (rowmax from RM) ----------------
#define FPAD 56
#define FTILE (128*FPAD*2)            // 14336 B per buf
#define FV_SMEM (6*FTILE + 512 + 1024)

__global__ void __launch_bounds__(256, 2) pv_fused(
    const float* __restrict__ S, const bf16* __restrict__ Vt, bf16* __restrict__ Y3,
    const unsigned* __restrict__ RM)
{
    extern __shared__ __align__(16) char smem[];
    bf16* shA = reinterpret_cast<bf16*>(smem);
    bf16* shB = reinterpret_cast<bf16*>(smem + 3 * FTILE);
    float* mrow = reinterpret_cast<float*>(smem + 6 * FTILE);   // 128
    float* sums = mrow + 128;                                   // 256
    const uint32_t sAaddr = smem_u32(shA);
    const uint32_t sBaddr = smem_u32(shB);

    const int z  = blockIdx.x;
    const int my = (gridDim.y - 1) - blockIdx.y;
    const int m0 = my * 128;
    const int kEnd = m0 + 128;
    const int nch = kEnd >> 4;

    const float* Sb = S + (long long)z * SEQ * SEQ + (long long)m0 * SEQ;
    const bf16*  Vb = Vt + (long long)(z >> 2) * HD * 3 * SEQ;
    bf16* Yb = Y3 + (long long)(z >> 4) * SEQ * 3 * DMODEL + (long long)(z & 15) * 3 * HD;

    const int t = threadIdx.x;
    const int w = t >> 5, lane = t & 31;

    if (t < 128) mrow[t] = dec_f(RM[(long long)z * SEQ + m0 + t]);
    __syncthreads();

    const int frow = t >> 1, fhalf = t & 1;
    const float mreg = mrow[frow];
    float sumReg = 0.0f;
    const float* fS = Sb + (long long)frow * SEQ + fhalf * 8;
    uint32_t* aU = reinterpret_cast<uint32_t*>(shA) + frow * (FPAD / 2) + fhalf * 12;
    const int aBufU = FTILE / 4;

    const bf16* gV = Vb + (long long)frow * (3 * SEQ) + fhalf * 24;
    const uint32_t dV = sBaddr + (frow * FPAD + fhalf * 24) * 2;

    const int wr = w >> 2, wc = w & 3;
    const int mBase = wr * 64, nBase = wc * 32;
    const int aRow = mBase + (lane & 7) + ((lane >> 3) & 1) * 8;
    const int aK   = (lane >> 4) * 8;
    const int bRow = nBase + (lane & 7) + ((lane >> 4) & 1) * 8;
    const int bK   = ((lane >> 3) & 1) * 8;

    float acc[4][4][4];
    #pragma unroll
    for (int i = 0; i < 4; i++)
        #pragma unroll
        for (int j = 0; j < 4; j++)
            #pragma unroll
            for (int q = 0; q < 4; q++) acc[i][j][q] = 0.0f;

    // split fillA: loadS issues gmem loads into regs; procA consumes after mma
    float4 s0, s1;
    auto loadS = [&](int c) {
        const float* sp = fS + c * 16;
        s0 = *reinterpret_cast<const float4*>(sp);
        s1 = *reinterpret_cast<const float4*>(sp + 4);
    };
    auto procA = [&](int buf) {
        float pv[8];
        pv[0] = exp2f(s0.x - mreg); pv[1] = exp2f(s0.y - mreg);
        pv[2] = exp2f(s0.z - mreg); pv[3] = exp2f(s0.w - mreg);
        pv[4] = exp2f(s1.x - mreg); pv[5] = exp2f(s1.y - mreg);
        pv[6] = exp2f(s1.z - mreg); pv[7] = exp2f(s1.w - mreg);
        #pragma unroll
        for (int j = 0; j < 8; j++) sumReg += pv[j];
        uint32_t* dst = aU + buf * aBufU;
        #pragma unroll
        for (int j = 0; j < 4; j++) {
            bf16 h0, l0, h1, l1;
            split2(pv[2 * j],     h0, l0);
            split2(pv[2 * j + 1], h1, l1);
            dst[3 * j]     = pk(h0, l0);
            dst[3 * j + 1] = pk(h0, h1);
            dst[3 * j + 2] = pk(l1, h1);
        }
    };
    auto loadV = [&](int c, int buf) {
        const bf16* pv = gV + c * 48;
        const uint32_t d = dV + buf * FTILE;
        CP_ASYNC16(d,      pv);
        CP_ASYNC16(d + 16, pv + 8);
        CP_ASYNC16(d + 32, pv + 16);
    };

    loadS(0); procA(0);
    loadS(1); procA(1);
    loadV(0, 0); CP_COMMIT();
    loadV(1, 1); CP_COMMIT();

    int buf = 0, nbuf = 2;
    for (int i = 0; i < nch; i++) {
        if (i < nch - 1) { CP_WAIT(1); } else { CP_WAIT(0); }
        __syncthreads();

        const bool pre = (i + 2 < nch);
        if (pre) { loadS(i + 2); loadV(i + 2, nbuf); }   // loads in flight
        CP_COMMIT();

        const uint32_t ab = sAaddr + buf * FTILE;
        const uint32_t bb = sBaddr + buf * FTILE;
        #pragma unroll
        for (int ks = 0; ks < 3; ks++) {
            uint32_t af[4][4], bfr[2][4];
            #pragma unroll
            for (int fm = 0; fm < 4; fm++)
                ldsm4(af[fm], ab + ((aRow + fm * 16) * FPAD + ks * 16 + aK) * 2);
            #pragma unroll
            for (int bg = 0; bg < 2; bg++)
                ldsm4(bfr[bg], bb + ((bRow + bg * 16) * FPAD + ks * 16 + bK) * 2);
            #pragma unroll
            for (int fm = 0; fm < 4; fm++)
                #pragma unroll
                for (int fn = 0; fn < 4; fn++)
                    mma16816(acc[fm][fn], af[fm], &bfr[fn >> 1][(fn & 1) * 2]);
        }

        if (pre) procA(nbuf);    // S loads have had the whole mma block to land

        buf = (buf == 2) ? 0 : buf + 1;
        nbuf = (nbuf == 2) ? 0 : nbuf + 1;
    }

    __syncthreads();
    sums[t] = sumReg;
    __syncthreads();
    if (t < 128) mrow[t] = 1.0f / (sums[2 * t] + sums[2 * t + 1]);
    __syncthreads();

    const int g = lane >> 2, tg = lane & 3;
    #pragma unroll
    for (int fm = 0; fm < 4; fm++) {
        #pragma unroll
        for (int fn = 0; fn < 4; fn++) {
            const int col = nBase + fn * 8 + tg * 2;
            #pragma unroll
            for (int half = 0; half < 2; half++) {
                const int row = mBase + fm * 16 + g + half * 8;
                const float inv = mrow[row];
                float v0 = acc[fm][fn][half * 2]     * inv;
                float v1 = acc[fm][fn][half * 2 + 1] * inv;
                bf16 h0, l0, h1, l1;
                split2(v0, h0, l0); split2(v1, h1, l1);
                uint32_t* dst = reinterpret_cast<uint32_t*>(
                    Yb + (long long)(m0 + row) * 3 * DMODEL + 3 * col);
                dst[0] = pk(h0, l0);
                dst[1] = pk(h0, h1);
                dst[2] = pk(l1, h1);
            }
        }
    }
}

// ---------------- fp32 -> triple-interleaved bf16 ----------------
template<bool ASIDE>
__global__ void split3_kernel(const float* __restrict__ in, bf16* __restrict__ o3, long long n4)
{
    long long i = (long long)blockIdx.x * blockDim.x + threadIdx.x;
    if (i >= n4) return;
    float4 v = reinterpret_cast<const float4*>(in)[i];
    bf16 h[4], l[4];
    split2(v.x, h[0], l[0]); split2(v.y, h[1], l[1]);
    split2(v.z, h[2], l[2]); split2(v.w, h[3], l[3]);
    uint32_t u[6];
    if (ASIDE) {
        u[0] = pk(h[0], l[0]); u[1] = pk(h[0], h[1]); u[2] = pk(l[1], h[1]);
        u[3] = pk(h[2], l[2]); u[4] = pk(h[2], h[3]); u[5] = pk(l[3], h[3]);
    } else {
        u[0] = pk(h[0], h[0]); u[1] = pk(l[0], h[1]); u[2] = pk(h[1], l[1]);
        u[3] = pk(h[2], h[2]); u[4] = pk(l[2], h[3]); u[5] = pk(h[3], l[3]);
    }
    uint2* dst = reinterpret_cast<uint2*>(o3 + i * 12);
    dst[0] = make_uint2(u[0], u[1]);
    dst[1] = make_uint2(u[2], u[3]);
    dst[2] = make_uint2(u[4], u[5]);
}

// ---------------- launch ----------------
extern "C" void kernel_launch(void* const* d_in, const int* in_sizes, int n_in,
                              void* d_out, int out_size)
{
    const float* x     = (const float*)d_in[0];
    const float* q_w   = (const float*)d_in[1];
    const float* k_w   = (const float*)d_in[2];
    const float* v_w   = (const float*)d_in[3];
    const float* out_w = (const float*)d_in[4];
    const float* q_g   = (const float*)d_in[5];
    float* out = (float*)d_out;

    static bool init = false;
    static bf16 *x3,*qw3,*kw3,*vw3,*ow3,*Qp3,*Kp3,*Vt3,*Y3;
    static float *Sb;
    static unsigned *RM;
    if (!init) {
        cudaGetSymbolAddress((void**)&x3,  g_x3);
        cudaGetSymbolAddress((void**)&qw3, g_qw3);
        cudaGetSymbolAddress((void**)&kw3, g_kw3);
        cudaGetSymbolAddress((void**)&vw3, g_vw3);
        cudaGetSymbolAddress((void**)&ow3, g_ow3);
        cudaGetSymbolAddress((void**)&Qp3, g_Qp3);
        cudaGetSymbolAddress((void**)&Kp3, g_Kp3);
        cudaGetSymbolAddress((void**)&Vt3, g_Vt3);
        cudaGetSymbolAddress((void**)&Sb,  g_S);
        cudaGetSymbolAddress((void**)&Y3,  g_Y3);
        cudaGetSymbolAddress((void**)&RM,  g_RM);
        cudaFuncSetAttribute(qkv_kernel, cudaFuncAttributeMaxDynamicSharedMemorySize, QKV_SMEM);
        cudaFuncSetAttribute(mm_kernel<false,false>, cudaFuncAttributeMaxDynamicSharedMemorySize, MM_SMEM);
        cudaFuncSetAttribute(mm_kernel<true, false>, cudaFuncAttributeMaxDynamicSharedMemorySize, MM_SMEM);
        cudaFuncSetAttribute(pv_fused, cudaFuncAttributeMaxDynamicSharedMemorySize, FV_SMEM);
        init = true;
    }

    const long long SS = (long long)SEQ * SEQ;
    const float scale2 = 0.08838834764831845f * 1.4426950408889634f;

    rm_init<<<BATCH*NH*SEQ/256, 256>>>(RM);
    {
        long long n4;
        n4 = (long long)MTOK * DMODEL / 4;   split3_kernel<true ><<<(unsigned)((n4+255)/256),256>>>(x, x3, n4);
        n4 = (long long)DMODEL * DMODEL / 4; split3_kernel<false><<<(unsigned)((n4+255)/256),256>>>(q_w, qw3, n4);
        n4 = (long long)NKV*HD * DMODEL / 4; split3_kernel<false><<<(unsigned)((n4+255)/256),256>>>(k_w, kw3, n4);
        n4 = (long long)NKV*HD * DMODEL / 4; split3_kernel<false><<<(unsigned)((n4+255)/256),256>>>(v_w, vw3, n4);
        n4 = (long long)DMODEL * DMODEL / 4; split3_kernel<false><<<(unsigned)((n4+255)/256),256>>>(out_w, ow3, n4);
    }

    // fused QKV projection + norm/rope/gain/split
    qkv_kernel<<<dim3(24, MTOK/128, 1), 256, QKV_SMEM>>>(
        x3, qw3, kw3, vw3, Qp3, Kp3, Vt3, q_g);

    // scores = Qp @ Kp^T * scale * log2e, causal, rowmax to RM. K3 = 384
    mm_kernel<true,false><<<dim3(SEQ/128, SEQ/128, BATCH*NH), 256, MM_SMEM>>>(
        Qp3, Kp3, Sb, nullptr, RM, 3*HD, 3*HD, 3*HD, SEQ,
        (long long)SEQ*3*HD, (long long)SEQ*3*HD, SS, 0, 4, 1, scale2);

    // fused softmax + P@V -> Y3 triple bf16 (occ 2, S-prefetch)
    pv_fused<<<dim3(BATCH*NH, SEQ/128, 1), 256, FV_SMEM>>>(Sb, Vt3, Y3, RM);

    // out = Y @ out_w^T (fp32 into d_out)
    mm_kernel<false,false><<<dim3(DMODEL/128, MTOK/128, 1), 256, MM_SMEM>>>(
        Y3, ow3, out, nullptr, nullptr, 3*DMODEL, 3*DMODEL, 3*DMODEL, DMODEL, 0,0,0,0, 1,1, 1.0f);
}

// round 17
// speedup vs baseline: 1.0243x; 1.0243x over previous
#include <cuda_runtime.h>
#include <cuda_bf16.h>
#include <cuda_fp16.h>
#include <cstdint>
#include <math.h>

#define BATCH 2
#define SEQ   2048
#define DMODEL 2048
#define NH    16
#define NKV   4
#define HD    128
#define ROPE  64
#define MTOK  (BATCH*SEQ)
#define EPSV  1.1920929e-07f

typedef __nv_bfloat16 bf16;

// ---------------- scratch ----------------
__device__ bf16 g_x3 [(size_t)MTOK*3*DMODEL];
__device__ bf16 g_qw3[(size_t)DMODEL*3*DMODEL];
__device__ bf16 g_kw3[(size_t)NKV*HD*3*DMODEL];
__device__ bf16 g_vw3[(size_t)NKV*HD*3*DMODEL];
__device__ bf16 g_ow3[(size_t)DMODEL*3*DMODEL];
__device__ bf16 g_Qp3[(size_t)BATCH*NH*SEQ*3*HD];
__device__ bf16 g_Kp3[(size_t)BATCH*NKV*SEQ*3*HD];
__device__ bf16 g_Vt3[(size_t)BATCH*NKV*HD*3*SEQ];
__device__ __half g_E[(size_t)BATCH*NH*SEQ*SEQ];      // exp2(s - m_subtile), fp16
__device__ float g_TM[(size_t)BATCH*NH*SEQ*64];       // per (row, 32-col subtile) max
__device__ bf16 g_Y3 [(size_t)MTOK*3*DMODEL];
__device__ unsigned g_RM[(size_t)BATCH*NH*SEQ];       // encoded global row maxima

__device__ __forceinline__ void split2(float v, bf16& h, bf16& l) {
    h = __float2bfloat16_rn(v);
    l = __float2bfloat16_rn(v - __bfloat162float(h));
}
__device__ __forceinline__ uint32_t pk(bf16 a, bf16 b) {
    return (uint32_t)__bfloat16_as_ushort(a) | ((uint32_t)__bfloat16_as_ushort(b) << 16);
}
__device__ __forceinline__ unsigned enc_f(float f) {
    int i = __float_as_int(f);
    return (i >= 0) ? ((unsigned)i | 0x80000000u) : ~(unsigned)i;
}
__device__ __forceinline__ float dec_f(unsigned k) {
    int i = (k & 0x80000000u) ? (int)(k ^ 0x80000000u) : (int)(~k);
    return __int_as_float(i);
}
__device__ __forceinline__ void w3A(bf16* p, float v0, float v1) {
    bf16 h0, l0, h1, l1; split2(v0, h0, l0); split2(v1, h1, l1);
    uint32_t* u = reinterpret_cast<uint32_t*>(p);
    u[0] = pk(h0, l0); u[1] = pk(h0, h1); u[2] = pk(l1, h1);
}
__device__ __forceinline__ void w3B(bf16* p, float v0, float v1) {
    bf16 h0, l0, h1, l1; split2(v0, h0, l0); split2(v1, h1, l1);
    uint32_t* u = reinterpret_cast<uint32_t*>(p);
    u[0] = pk(h0, h0); u[1] = pk(l0, h1); u[2] = pk(h1, l1);
}

// ---------------- PTX helpers (baseline PTX only) ----------------
__device__ __forceinline__ uint32_t smem_u32(const void* p) {
    uint32_t a;
    asm("{ .reg .u64 t; cvta.to.shared.u64 t, %1; cvt.u32.u64 %0, t; }" : "=r"(a) : "l"(p));
    return a;
}
__device__ __forceinline__ void ldsm4(uint32_t* r, uint32_t addr) {
    asm volatile("ldmatrix.sync.aligned.m8n8.x4.shared.b16 {%0,%1,%2,%3}, [%4];"
                 : "=r"(r[0]), "=r"(r[1]), "=r"(r[2]), "=r"(r[3]) : "r"(addr));
}
__device__ __forceinline__ void mma16816(float* c, const uint32_t* a, const uint32_t* b) {
    asm volatile(
        "mma.sync.aligned.m16n8k16.row.col.f32.bf16.bf16.f32 "
        "{%0,%1,%2,%3}, {%4,%5,%6,%7}, {%8,%9}, {%0,%1,%2,%3};"
        : "+f"(c[0]), "+f"(c[1]), "+f"(c[2]), "+f"(c[3])
        : "r"(a[0]), "r"(a[1]), "r"(a[2]), "r"(a[3]), "r"(b[0]), "r"(b[1]));
}
#define CP_ASYNC16(dst, src) \
    asm volatile("cp.async.cg.shared.global [%0], [%1], 16;" :: "r"(dst), "l"(src) : "memory")
#define CP_COMMIT() asm volatile("cp.async.commit_group;" ::: "memory")
#define CP_WAIT(n)  asm volatile("cp.async.wait_group %0;" :: "n"(n) : "memory")

// ---------------- settled GEMM config ----------------
#define PADK 40
#define TILEB (128*PADK*2)
#define MM_SMEM (3*TILEB*2)
#define QKV_SMEM (128*132*4)

struct MMState {
    uint32_t sAaddr, sBaddr;
    int aRow, aK, bRow, bK;
};

__device__ __forceinline__ void mm_mainloop(
    const bf16* gA, const bf16* gB, uint32_t dA, uint32_t dB,
    const MMState& st, int nc, float acc[4][4][4])
{
    #pragma unroll
    for (int j = 0; j < 2; j++) {
        if (j < nc) {
            const bf16* pA = gA + j * 32;
            const bf16* pB = gB + j * 32;
            CP_ASYNC16(dA + j * TILEB, pA);      CP_ASYNC16(dA + j * TILEB + 16, pA + 8);
            CP_ASYNC16(dB + j * TILEB, pB);      CP_ASYNC16(dB + j * TILEB + 16, pB + 8);
        }
        CP_COMMIT();
    }

    int buf = 0, nbuf = 2;
    for (int i = 0; i < nc; i++) {
        if (i < nc - 1) { CP_WAIT(1); } else { CP_WAIT(0); }
        __syncthreads();

        if (i + 2 < nc) {
            const bf16* pA = gA + (i + 2) * 32;
            const bf16* pB = gB + (i + 2) * 32;
            CP_ASYNC16(dA + nbuf * TILEB, pA);      CP_ASYNC16(dA + nbuf * TILEB + 16, pA + 8);
            CP_ASYNC16(dB + nbuf * TILEB, pB);      CP_ASYNC16(dB + nbuf * TILEB + 16, pB + 8);
        }
        CP_COMMIT();

        const uint32_t ab = st.sAaddr + buf * TILEB;
        const uint32_t bb = st.sBaddr + buf * TILEB;
        #pragma unroll
        for (int ks = 0; ks < 2; ks++) {
            uint32_t af[4][4], bfr[2][4];
            #pragma unroll
            for (int fm = 0; fm < 4; fm++)
                ldsm4(af[fm], ab + ((st.aRow + fm * 16) * PADK + ks * 16 + st.aK) * 2);
            #pragma unroll
            for (int bg = 0; bg < 2; bg++)
                ldsm4(bfr[bg], bb + ((st.bRow + bg * 16) * PADK + ks * 16 + st.bK) * 2);
            #pragma unroll
            for (int fm = 0; fm < 4; fm++)
                #pragma unroll
                for (int fn = 0; fn < 4; fn++)
                    mma16816(acc[fm][fn], af[fm], &bfr[fn >> 1][(fn & 1) * 2]);
        }

        buf = (buf == 2) ? 0 : buf + 1;
        nbuf = (nbuf == 2) ? 0 : nbuf + 1;
    }
}

__device__ __forceinline__ void mm_setup(MMState& st, char* smem, int t)
{
    st.sAaddr = smem_u32(smem);
    st.sBaddr = st.sAaddr + 3 * TILEB;
    const int w = t >> 5, lane = t & 31;
    const int wr = w >> 2, wc = w & 3;
    st.aRow = wr * 64 + (lane & 7) + ((lane >> 3) & 1) * 8;
    st.aK   = (lane >> 4) * 8;
    st.bRow = wc * 32 + (lane & 7) + ((lane >> 4) & 1) * 8;
    st.bK   = ((lane >> 3) & 1) * 8;
}

// ---------------- fused QKV projection + RMSNorm + RoPE + gain + split ----------------
__global__ void __launch_bounds__(256, 2) qkv_kernel(
    const bf16* __restrict__ X,
    const bf16* __restrict__ QW, const bf16* __restrict__ KW, const bf16* __restrict__ VW,
    bf16* __restrict__ Qp3, bf16* __restrict__ Kp3, bf16* __restrict__ Vt3,
    const float* __restrict__ gain)
{
    extern __shared__ __align__(16) char smem[];
    const int t = threadIdx.x;

    const int xt = blockIdx.x;
    const bf16* B;
    if (xt < 16)      B = QW;
    else if (xt < 20) B = KW;
    else              B = VW;
    const int n0 = (xt < 16) ? xt * 128 : ((xt < 20) ? (xt - 16) * 128 : (xt - 20) * 128);

    const int m0 = blockIdx.y * 128;
    const int K3 = 3 * DMODEL;
    const int nc = K3 >> 5;

    MMState st; mm_setup(st, smem, t);

    const int lr = t >> 1;
    const int lc = (t & 1) * 2;
    const bf16* gA = X + (long long)(m0 + lr) * K3 + lc * 8;
    const bf16* gB = B + (long long)(n0 + lr) * K3 + lc * 8;
    const uint32_t dA = st.sAaddr + (lr * PADK + lc * 8) * 2;
    const uint32_t dB = st.sBaddr + (lr * PADK + lc * 8) * 2;

    float acc[4][4][4];
    #pragma unroll
    for (int i = 0; i < 4; i++)
        #pragma unroll
        for (int j = 0; j < 4; j++)
            #pragma unroll
            for (int q = 0; q < 4; q++) acc[i][j][q] = 0.0f;

    mm_mainloop(gA, gB, dA, dB, st, nc, acc);

    __syncthreads();
    float* sm = reinterpret_cast<float*>(smem);
    {
        const int w = t >> 5, lane = t & 31;
        const int wr = w >> 2, wc = w & 3;
        const int g = lane >> 2, tg = lane & 3;
        #pragma unroll
        for (int fm = 0; fm < 4; fm++)
            #pragma unroll
            for (int fn = 0; fn < 4; fn++)
                #pragma unroll
                for (int half = 0; half < 2; half++) {
                    const int row = wr * 64 + fm * 16 + g + half * 8;
                    const int col = wc * 32 + fn * 8 + tg * 2;
                    float2 f;
                    f.x = acc[fm][fn][half * 2];
                    f.y = acc[fm][fn][half * 2 + 1];
                    *reinterpret_cast<float2*>(&sm[row * 132 + col]) = f;
                }
    }
    __syncthreads();

    const int r = t >> 1, ch = t & 1, c0 = ch * 64;
    const int mg = m0 + r;
    const int b = mg / SEQ, s = mg % SEQ;
    const float* row = &sm[r * 132];

    if (xt < 20) {
        float ss = 0.0f;
        #pragma unroll
        for (int j = 0; j < 64; j += 4) {
            float4 v = *reinterpret_cast<const float4*>(row + c0 + j);
            ss += v.x * v.x + v.y * v.y + v.z * v.z + v.w * v.w;
        }
        ss += __shfl_xor_sync(0xFFFFFFFFu, ss, 1);
        const float rinv = rsqrtf(ss * (1.0f / 128.0f) + EPSV);

        const bool isQ = (xt < 16);
        const int h = isQ ? xt : xt - 16;
        const float gn = isQ ? gain[h] : 1.0f;
        bf16* base = isQ
            ? Qp3 + ((size_t)(b * NH  + h) * SEQ + s) * (3 * HD)
            : Kp3 + ((size_t)(b * NKV + h) * SEQ + s) * (3 * HD);

        if (ch == 0) {
            #pragma unroll 4
            for (int j = 0; j < 32; j += 2) {
                float o0[2], o1[2];
                #pragma unroll
                for (int q = 0; q < 2; q++) {
                    const int jj = j + q;
                    float x1 = row[jj] * rinv;
                    float x2 = row[jj + 32] * rinv;
                    float inv_freq = powf(10000.0f, -(float)jj / 32.0f);
                    float ang = (float)s * inv_freq;
                    float c = cosf(ang), sn = sinf(ang);
                    o0[q] = (x1 * c + x2 * sn) * gn;
                    o1[q] = (-x1 * sn + x2 * c) * gn;
                }
                if (isQ) { w3A(base + 3 * j, o0[0], o0[1]); w3A(base + 3 * (j + 32), o1[0], o1[1]); }
                else     { w3B(base + 3 * j, o0[0], o0[1]); w3B(base + 3 * (j + 32), o1[0], o1[1]); }
            }
        } else {
            #pragma unroll 8
            for (int j = 0; j < 64; j += 2) {
                float v0 = row[64 + j]     * rinv * gn;
                float v1 = row[64 + j + 1] * rinv * gn;
                if (isQ) w3A(base + 3 * (64 + j), v0, v1);
                else     w3B(base + 3 * (64 + j), v0, v1);
            }
        }
    } else {
        const int h = xt - 20;
        #pragma unroll 8
        for (int j = 0; j < 64; j++) {
            const int d = c0 + j;
            float v = row[d];
            bf16 hh, ll; split2(v, hh, ll);
            bf16* o = Vt3 + ((size_t)(b * NKV + h) * HD + d) * (3 * SEQ) + 3 * s;
            o[0] = hh; o[1] = hh; o[2] = ll;
        }
    }
}

// ---------------- score GEMM: causal, epilogue exp2 per 32-col subtile -> fp16 E + TM + RM ----------------
__global__ void __launch_bounds__(256, 2) score_kernel(
    const bf16* __restrict__ A, const bf16* __restrict__ B,
    __half* __restrict__ E, float* __restrict__ TM, unsigned* __restrict__ RM,
    float alpha)
{
    extern __shared__ __align__(16) char smem[];
    const int t = threadIdx.x;

    const int z = blockIdx.z;
    A += (long long)z * (SEQ * 3 * HD);
    B += (long long)(z / 4) * (SEQ * 3 * HD);
    __half* Ez = E + (long long)z * SEQ * SEQ;

    const int m0 = blockIdx.y * 128;
    const int n0 = blockIdx.x * 128;
    if (n0 > m0 + 127) return;

    MMState st; mm_setup(st, smem, t);

    const int lr = t >> 1;
    const int lc = (t & 1) * 2;
    const int K3 = 3 * HD;
    const int nc = K3 >> 5;

    const bf16* gA = A + (long long)(m0 + lr) * K3 + lc * 8;
    const bf16* gB = B + (long long)(n0 + lr) * K3 + lc * 8;
    const uint32_t dA = st.sAaddr + (lr * PADK + lc * 8) * 2;
    const uint32_t dB = st.sBaddr + (lr * PADK + lc * 8) * 2;

    float acc[4][4][4];
    #pragma unroll
    for (int i = 0; i < 4; i++)
        #pragma unroll
        for (int j = 0; j < 4; j++)
            #pragma unroll
            for (int q = 0; q < 4; q++) acc[i][j][q] = 0.0f;

    mm_mainloop(gA, gB, dA, dB, st, nc, acc);

    const int w = t >> 5, lane = t & 31;
    const int wr = w >> 2, wc = w & 3;
    const int mBase = wr * 64, nBase = wc * 32;
    const int g = lane >> 2, tg = lane & 3;
    const int subIdx = ((n0 + nBase) >> 5);   // this warp's 32-col subtile index (0..63)

    #pragma unroll
    for (int fm = 0; fm < 4; fm++) {
        float val[4][2][2];     // [fn][half][pair]
        float rmax[2];
        rmax[0] = -3.4e38f; rmax[1] = -3.4e38f;
        #pragma unroll
        for (int fn = 0; fn < 4; fn++) {
            const int col = n0 + nBase + fn * 8 + tg * 2;
            #pragma unroll
            for (int half = 0; half < 2; half++) {
                const int row = m0 + mBase + fm * 16 + g + half * 8;
                float v0 = acc[fm][fn][half * 2]     * alpha;
                float v1 = acc[fm][fn][half * 2 + 1] * alpha;
                if (col     > row) v0 = -1e30f;
                if (col + 1 > row) v1 = -1e30f;
                val[fn][half][0] = v0;
                val[fn][half][1] = v1;
                rmax[half] = fmaxf(rmax[half], fmaxf(v0, v1));
            }
        }
        #pragma unroll
        for (int half = 0; half < 2; half++) {
            // m = max over THIS warp's 32 columns for this row (lanes tg 0..3)
            float m = rmax[half];
            m = fmaxf(m, __shfl_xor_sync(0xFFFFFFFFu, m, 1));
            m = fmaxf(m, __shfl_xor_sync(0xFFFFFFFFu, m, 2));
            const int row = m0 + mBase + fm * 16 + g + half * 8;
            if (tg == 0) {
                if (m > -1e29f)   // only real maxima feed the global rowmax
                    atomicMax(RM + (long long)z * SEQ + row, enc_f(m));
                TM[((long long)z * SEQ + row) * 64 + subIdx] = m;
            }
            #pragma unroll
            for (int fn = 0; fn < 4; fn++) {
                const int col = n0 + nBase + fn * 8 + tg * 2;
                __half2 e;
                e.x = __float2half_rn(exp2f(val[fn][half][0] - m));
                e.y = __float2half_rn(exp2f(val[fn][half][1] - m));
                *reinterpret_cast<__half2*>(Ez + (long long)row * SEQ + col) = e;
            }
        }
    }
}

// ---------------- out-proj GEMM (fp32 out) ----------------
__global__ void __launch_bounds__(256, 2) mm_kernel(
    const bf16* __restrict__ A, const bf16* __restrict__ B,
    float* __restrict__ C, int K3, int lda, int ldb, int ldc)
{
    extern __shared__ __align__(16) char smem[];
    const int t = threadIdx.x;

    const int m0 = blockIdx.y * 128;
    const int n0 = blockIdx.x * 128;

    MMState st; mm_setup(st, smem, t);

    const int lr = t >> 1;
    const int lc = (t & 1) * 2;
    const int nc = K3 >> 5;

    const bf16* gA = A + (long long)(m0 + lr) * lda + lc * 8;
    const bf16* gB = B + (long long)(n0 + lr) * ldb + lc * 8;
    const uint32_t dA = st.sAaddr + (lr * PADK + lc * 8) * 2;
    const uint32_t dB = st.sBaddr + (lr * PADK + lc * 8) * 2;

    float acc[4][4][4];
    #pragma unroll
    for (int i = 0; i < 4; i++)
        #pragma unroll
        for (int j = 0; j < 4; j++)
            #pragma unroll
            for (int q = 0; q < 4; q++) acc[i][j][q] = 0.0f;

    mm_mainloop(gA, gB, dA, dB, st, nc, acc);

    const int w = t >> 5, lane = t & 31;
    const int wr = w >> 2, wc = w & 3;
    const int g = lane >> 2, tg = lane & 3;
    #pragma unroll
    for (int fm = 0; fm < 4; fm++)
        #pragma unroll
        for (int fn = 0; fn < 4; fn++) {
            const int col = n0 + wc * 32 + fn * 8 + tg * 2;
            #pragma unroll
            for (int half = 0; half < 2; half++) {
                const int row = m0 + wr * 64 + fm * 16 + g + half * 8;
                float2 f;
                f.x = acc[fm][fn][half * 2];
                f.y = acc[fm][fn][half * 2 + 1];
                *reinterpret_cast<float2*>(C + (long long)row * ldc + col) = f;
            }
        }
}

// ---------------- rowmax init ----------------
__global__ void rm_init(unsigned* __restrict__ RM)
{
    RM[blockIdx.x * 256 + threadIdx.x] = 0u;
}

// ---------------- fused softmax + PV kernel (E fp16, TM per-subtile rescale) ----------------
#define FPAD 56
#define FTILE (128*FPAD*2)
#define FV_SMEM (6*FTILE + 512 + 1024)

__global__ void __launch_bounds__(256, 2) pv_fused(
    const __half* __restrict__ E, const float* __restrict__ TM,
    const bf16* __restrict__ Vt, bf16* __restrict__ Y3,
    const unsigned* __restrict__ RM)
{
    extern __shared__ __align__(16) char smem[];
    bf16* shA = reinterpret_cast<bf16*>(smem);
    bf16* shB = reinterpret_cast<bf16*>(smem + 3 * FTILE);
    float* mrow = reinterpret_cast<float*>(smem + 6 * FTILE);   // 128
    float* sums = mrow + 128;                                   // 256
    const uint32_t sAaddr = smem_u32(shA);
    const uint32_t sBaddr = smem_u32(shB);

    const int z  = blockIdx.x;
    const int my = (gridDim.y - 1) - blockIdx.y;
    const int m0 = my * 128;
    const int kEnd = m0 + 128;
    const int nch = kEnd >> 4;

    const __half* Eb = E + (long long)z * SEQ * SEQ + (long long)m0 * SEQ;
    const bf16*  Vb = Vt + (long long)(z >> 2) * HD * 3 * SEQ;
    bf16* Yb = Y3 + (long long)(z >> 4) * SEQ * 3 * DMODEL + (long long)(z & 15) * 3 * HD;

    const int t = threadIdx.x;
    const int w = t >> 5, lane = t & 31;

    if (t < 128) mrow[t] = dec_f(RM[(long long)z * SEQ + m0 + t]);
    __syncthreads();

    const int frow = t >> 1, fhalf = t & 1;
    const float mreg = mrow[frow];
    float sumReg = 0.0f;
    const __half* fE = Eb + (long long)frow * SEQ + fhalf * 8;
    const float* tmr = TM + ((long long)z * SEQ + m0 + frow) * 64;
    uint32_t* aU = reinterpret_cast<uint32_t*>(shA) + frow * (FPAD / 2) + fhalf * 12;
    const int aBufU = FTILE / 4;

    const bf16* gV = Vb + (long long)frow * (3 * SEQ) + fhalf * 24;
    const uint32_t dV = sBaddr + (frow * FPAD + fhalf * 24) * 2;

    const int wr = w >> 2, wc = w & 3;
    const int mBase = wr * 64, nBase = wc * 32;
    const int aRow = mBase + (lane & 7) + ((lane >> 3) & 1) * 8;
    const int aK   = (lane >> 4) * 8;
    const int bRow = nBase + (lane & 7) + ((lane >> 4) & 1) * 8;
    const int bK   = ((lane >> 3) & 1) * 8;

    float acc[4][4][4];
    #pragma unroll
    for (int i = 0; i < 4; i++)
        #pragma unroll
        for (int j = 0; j < 4; j++)
            #pragma unroll
            for (int q = 0; q < 4; q++) acc[i][j][q] = 0.0f;

    // fillA: p = e * exp2(m_sub - m_row); one exp2 per 16-elem chunk.
    // chunk c covers cols [c*16, c*16+16) -> subtile index c>>1 (each thread's
    // 8-col half stays inside that subtile: fhalf*8 within 16-col chunk).
    auto fillA = [&](int c, int buf) {
        const float fscale = exp2f(tmr[c >> 1] - mreg);
        uint4 eu = *reinterpret_cast<const uint4*>(fE + c * 16);   // 8 halves
        const __half2* eh = reinterpret_cast<const __half2*>(&eu);
        float pv[8];
        #pragma unroll
        for (int j = 0; j < 4; j++) {
            float2 ef = __half22float2(eh[j]);
            pv[2 * j]     = ef.x * fscale;
            pv[2 * j + 1] = ef.y * fscale;
        }
        #pragma unroll
        for (int j = 0; j < 8; j++) sumReg += pv[j];
        uint32_t* dst = aU + buf * aBufU;
        #pragma unroll
        for (int j = 0; j < 4; j++) {
            bf16 h0, l0, h1, l1;
            split2(pv[2 * j],     h0, l0);
            split2(pv[2 * j + 1], h1, l1);
            dst[3 * j]     = pk(h0, l0);
            dst[3 * j + 1] = pk(h0, h1);
            dst[3 * j + 2] = pk(l1, h1);
        }
    };
    auto loadV = [&](int c, int buf) {
        const bf16* pv = gV + c * 48;
        const uint32_t d = dV + buf * FTILE;
        CP_ASYNC16(d,      pv);
        CP_ASYNC16(d + 16, pv + 8);
        CP_ASYNC16(d + 32, pv + 16);
    };

    fillA(0, 0); fillA(1, 1);
    loadV(0, 0); CP_COMMIT();
    loadV(1, 1); CP_COMMIT();

    int buf = 0, nbuf = 2;
    for (int i = 0; i < nch; i++) {
        if (i < nch - 1) { CP_WAIT(1); } else { CP_WAIT(0); }
        __syncthreads();

        if (i + 2 < nch) { fillA(i + 2, nbuf); loadV(i + 2, nbuf); }
        CP_COMMIT();

        const uint32_t ab = sAaddr + buf * FTILE;
        const uint32_t bb = sBaddr + buf * FTILE;
        #pragma unroll
        for (int ks = 0; ks < 3; ks++) {
            uint32_t af[4][4], bfr[2][4];
            #pragma unroll
            for (int fm = 0; fm < 4; fm++)
                ldsm4(af[fm], ab + ((aRow + fm * 16) * FPAD + ks * 16 + aK) * 2);
            #pragma unroll
            for (int bg = 0; bg < 2; bg++)
                ldsm4(bfr[bg], bb + ((bRow + bg * 16) * FPAD + ks * 16 + bK) * 2);
            #pragma unroll
            for (int fm = 0; fm < 4; fm++)
                #pragma unroll
                for (int fn = 0; fn < 4; fn++)
                    mma16816(acc[fm][fn], af[fm], &bfr[fn >> 1][(fn & 1) * 2]);
        }

        buf = (buf == 2) ? 0 : buf + 1;
        nbuf = (nbuf == 2) ? 0 : nbuf + 1;
    }

    __syncthreads();
    sums[t] = sumReg;
    __syncthreads();
    if (t < 128) mrow[t] = 1.0f / (sums[2 * t] + sums[2 * t + 1]);
    __syncthreads();

    const int g = lane >> 2, tg = lane & 3;
    #pragma unroll
    for (int fm = 0; fm < 4; fm++) {
        #pragma unroll
        for (int fn = 0; fn < 4; fn++) {
            const int col = nBase + fn * 8 + tg * 2;
            #pragma unroll
            for (int half = 0; half < 2; half++) {
                const int row = mBase + fm * 16 + g + half * 8;
                const float inv = mrow[row];
                float v0 = acc[fm][fn][half * 2]     * inv;
                float v1 = acc[fm][fn][half * 2 + 1] * inv;
                bf16 h0, l0, h1, l1;
                split2(v0, h0, l0); split2(v1, h1, l1);
                uint32_t* dst = reinterpret_cast<uint32_t*>(
                    Yb + (long long)(m0 + row) * 3 * DMODEL + 3 * col);
                dst[0] = pk(h0, l0);
                dst[1] = pk(h0, h1);
                dst[2] = pk(l1, h1);
            }
        }
    }
}

// ---------------- fp32 -> triple-interleaved bf16 ----------------
template<bool ASIDE>
__global__ void split3_kernel(const float* __restrict__ in, bf16* __restrict__ o3, long long n4)
{
    long long i = (long long)blockIdx.x * blockDim.x + threadIdx.x;
    if (i >= n4) return;
    float4 v = reinterpret_cast<const float4*>(in)[i];
    bf16 h[4], l[4];
    split2(v.x, h[0], l[0]); split2(v.y, h[1], l[1]);
    split2(v.z, h[2], l[2]); split2(v.w, h[3], l[3]);
    uint32_t u[6];
    if (ASIDE) {
        u[0] = pk(h[0], l[0]); u[1] = pk(h[0], h[1]); u[2] = pk(l[1], h[1]);
        u[3] = pk(h[2], l[2]); u[4] = pk(h[2], h[3]); u[5] = pk(l[3], h[3]);
    } else {
        u[0] = pk(h[0], h[0]); u[1] = pk(l[0], h[1]); u[2] = pk(h[1], l[1]);
        u[3] = pk(h[2], h[2]); u[4] = pk(l[2], h[3]); u[5] = pk(h[3], l[3]);
    }
    uint2* dst = reinterpret_cast<uint2*>(o3 + i * 12);
    dst[0] = make_uint2(u[0], u[1]);
    dst[1] = make_uint2(u[2], u[3]);
    dst[2] = make_uint2(u[4], u[5]);
}

// ---------------- launch ----------------
extern "C" void kernel_launch(void* const* d_in, const int* in_sizes, int n_in,
                              void* d_out, int out_size)
{
    const float* x     = (const float*)d_in[0];
    const float* q_w   = (const float*)d_in[1];
    const float* k_w   = (const float*)d_in[2];
    const float* v_w   = (const float*)d_in[3];
    const float* out_w = (const float*)d_in[4];
    const float* q_g   = (const float*)d_in[5];
    float* out = (float*)d_out;

    static bool init = false;
    static bf16 *x3,*qw3,*kw3,*vw3,*ow3,*Qp3,*Kp3,*Vt3,*Y3;
    static __half *Eb;
    static float *TMb;
    static unsigned *RM;
    if (!init) {
        cudaGetSymbolAddress((void**)&x3,  g_x3);
        cudaGetSymbolAddress((void**)&qw3, g_qw3);
        cudaGetSymbolAddress((void**)&kw3, g_kw3);
        cudaGetSymbolAddress((void**)&vw3, g_vw3);
        cudaGetSymbolAddress((void**)&ow3, g_ow3);
        cudaGetSymbolAddress((void**)&Qp3, g_Qp3);
        cudaGetSymbolAddress((void**)&Kp3, g_Kp3);
        cudaGetSymbolAddress((void**)&Vt3, g_Vt3);
        cudaGetSymbolAddress((void**)&Eb,  g_E);
        cudaGetSymbolAddress((void**)&TMb, g_TM);
        cudaGetSymbolAddress((void**)&Y3,  g_Y3);
        cudaGetSymbolAddress((void**)&RM,  g_RM);
        cudaFuncSetAttribute(qkv_kernel, cudaFuncAttributeMaxDynamicSharedMemorySize, QKV_SMEM);
        cudaFuncSetAttribute(score_kernel, cudaFuncAttributeMaxDynamicSharedMemorySize, MM_SMEM);
        cudaFuncSetAttribute(mm_kernel, cudaFuncAttributeMaxDynamicSharedMemorySize, MM_SMEM);
        cudaFuncSetAttribute(pv_fused, cudaFuncAttributeMaxDynamicSharedMemorySize, FV_SMEM);
        init = true;
    }

    const float scale2 = 0.08838834764831845f * 1.4426950408889634f;

    rm_init<<<BATCH*NH*SEQ/256, 256>>>(RM);
    {
        long long n4;
        n4 = (long long)MTOK * DMODEL / 4;   split3_kernel<true ><<<(unsigned)((n4+255)/256),256>>>(x, x3, n4);
        n4 = (long long)DMODEL * DMODEL / 4; split3_kernel<false><<<(unsigned)((n4+255)/256),256>>>(q_w, qw3, n4);
        n4 = (long long)NKV*HD * DMODEL / 4; split3_kernel<false><<<(unsigned)((n4+255)/256),256>>>(k_w, kw3, n4);
        n4 = (long long)NKV*HD * DMODEL / 4; split3_kernel<false><<<(unsigned)((n4+255)/256),256>>>(v_w, vw3, n4);
        n4 = (long long)DMODEL * DMODEL / 4; split3_kernel<false><<<(unsigned)((n4+255)/256),256>>>(out_w, ow3, n4);
    }

    // fused QKV projection + norm/rope/gain/split
    qkv_kernel<<<dim3(24, MTOK/128, 1), 256, QKV_SMEM>>>(
        x3, qw3, kw3, vw3, Qp3, Kp3, Vt3, q_g);

    // scores -> exp2(s - m_subtile) fp16 + TM + RM
    score_kernel<<<dim3(SEQ/128, SEQ/128, BATCH*NH), 256, MM_SMEM>>>(
        Qp3, Kp3, Eb, TMb, RM, scale2);

    // fused softmax-rescale + P@V -> Y3 triple bf16 (occ 2)
    pv_fused<<<dim3(BATCH*NH, SEQ/128, 1), 256, FV_SMEM>>>(Eb, TMb, Vt3, Y3, RM);

    // out = Y @ out_w^T (fp32 into d_out)
    mm_kernel<<<dim3(DMODEL/128, MTOK/128, 1), 256, MM_SMEM>>>(
        Y3, ow3, out, 3*DMODEL, 3*DMODEL, 3*DMODEL, DMODEL);
}